// round 2
// baseline (speedup 1.0000x reference)
#include <cuda_runtime.h>
#include <math.h>

// Problem constants (fixed-shape problem)
#define BB 64
#define NN 431
#define CC 256
#define HH 56
#define WW 56
#define HW (HH*WW)
#define D0 128
#define D1 64
#define D2 5
#define K1 (D0+CC)   // 384
#define K2 (D1+CC)   // 320
#define TILE_P 64
#define NTILES ((NN + TILE_P - 1) / TILE_P)  // 7
#define THREADS 256

// smem: featT[256][64] + y0T[128][64] + wbuf(4096 floats, unioned with y1T[64][64])
#define SMEM_FLOATS ((CC + D0) * TILE_P + 4096)
#define SMEM_BYTES  (SMEM_FLOATS * 4)  // 114688 B -> 2 blocks/SM

// Transposed weights (scratch; __device__ globals per allocation rules)
__device__ float g_W0T[CC * D0];   // [k][o] 256x128
__device__ float g_W1T[K1 * D1];   // [k][o] 384x64
__device__ float g_W2T[K2 * 8];    // [k][o] 320x8 (o padded 5->8 with zeros)

__global__ void prep_kernel(const float* __restrict__ W0,
                            const float* __restrict__ W1,
                            const float* __restrict__ W2) {
    int i = blockIdx.x * blockDim.x + threadIdx.x;
    if (i < CC * D0) { int k = i / D0, o = i % D0; g_W0T[i] = W0[o * CC + k]; }
    if (i < K1 * D1) { int k = i / D1, o = i % D1; g_W1T[i] = W1[o * K1 + k]; }
    if (i < K2 * 8)  { int k = i / 8,  o = i % 8;  g_W2T[i] = (o < D2) ? W2[o * K2 + k] : 0.f; }
}

__global__ __launch_bounds__(THREADS, 2)
void maf_fused(const float* __restrict__ p, const float* __restrict__ cam,
               const float* __restrict__ sf,
               const float* __restrict__ b0, const float* __restrict__ b1,
               const float* __restrict__ b2, float* __restrict__ out)
{
    extern __shared__ float smem[];
    float* featT = smem;                         // [CC][TILE_P]
    float* y0T   = smem + CC * TILE_P;           // [D0][TILE_P]
    float* wbuf  = smem + (CC + D0) * TILE_P;    // 4096 floats (staging; later y1T)
    float* y1T   = wbuf;                         // [D1][TILE_P] after layer1

    const int tile = blockIdx.x;
    const int b    = blockIdx.y;
    const int tid  = threadIdx.x;

    // ---------------- gather: bilinear sample into featT[k][p] ----------------
    {
        const int tp = tid & 63;        // point within tile (lanes over points)
        const int cg = tid >> 6;        // channel group: 64 channels each
        const int n  = tile * TILE_P + tp;

        float w00 = 0.f, w10 = 0.f, w01 = 0.f, w11 = 0.f;
        int o00 = 0, o10 = 0, o01 = 0, o11 = 0;
        if (n < NN) {
            float s  = cam[b * 3 + 0];
            float tx = cam[b * 3 + 1];
            float ty = cam[b * 3 + 2];
            float gx = (s * (p[(b * NN + n) * 3 + 0] + tx) + 1.f) * (0.5f * (WW - 1));
            float gy = (s * (p[(b * NN + n) * 3 + 1] + ty) + 1.f) * (0.5f * (HH - 1));
            float x0f = floorf(gx), y0f = floorf(gy);
            float wx1 = gx - x0f, wy1 = gy - y0f;
            float wx0 = 1.f - wx1, wy0 = 1.f - wy1;
            // validity folded per-axis (matches reference's per-corner valid mask)
            if (!(x0f       >= 0.f && x0f       <= (float)(WW - 1))) wx0 = 0.f;
            if (!(x0f + 1.f >= 0.f && x0f + 1.f <= (float)(WW - 1))) wx1 = 0.f;
            if (!(y0f       >= 0.f && y0f       <= (float)(HH - 1))) wy0 = 0.f;
            if (!(y0f + 1.f >= 0.f && y0f + 1.f <= (float)(HH - 1))) wy1 = 0.f;
            int ix0 = (int)fminf(fmaxf(x0f,       0.f), (float)(WW - 1));
            int ix1 = (int)fminf(fmaxf(x0f + 1.f, 0.f), (float)(WW - 1));
            int iy0 = (int)fminf(fmaxf(y0f,       0.f), (float)(HH - 1));
            int iy1 = (int)fminf(fmaxf(y0f + 1.f, 0.f), (float)(HH - 1));
            int base = b * CC * HW;
            o00 = base + iy0 * WW + ix0;
            o10 = base + iy0 * WW + ix1;
            o01 = base + iy1 * WW + ix0;
            o11 = base + iy1 * WW + ix1;
            w00 = wx0 * wy0; w10 = wx1 * wy0; w01 = wx0 * wy1; w11 = wx1 * wy1;
        }
        const int c0 = cg * 64;
        #pragma unroll 4
        for (int cc = 0; cc < 64; cc++) {
            int off = (c0 + cc) * HW;
            float v = w00 * __ldg(sf + o00 + off) + w10 * __ldg(sf + o10 + off)
                    + w01 * __ldg(sf + o01 + off) + w11 * __ldg(sf + o11 + off);
            featT[(c0 + cc) * TILE_P + tp] = v;  // lanes over points -> conflict-free
        }
    }

    const int og   = tid >> 5;     // warp id 0..7
    const int lane = tid & 31;
    const int p0   = lane * 2;     // 2 points per thread

    // ---------------- layer0: 128 outs, K=256. Thread tile 16o x 2p ----------------
    float a0[16][2];
    #pragma unroll
    for (int i = 0; i < 16; i++) {
        float bv = __ldg(&b0[og * 16 + i]);
        a0[i][0] = bv; a0[i][1] = bv;
    }

    for (int kc = 0; kc < CC; kc += 32) {
        __syncthreads();   // first iter: also covers featT gather writes
        {   // stage W0T chunk [32k][128o] = 4096 floats
            float4* dst = (float4*)wbuf;
            const float4* src = (const float4*)(g_W0T + kc * D0);
            #pragma unroll
            for (int t = 0; t < 4; t++) dst[tid + t * THREADS] = src[tid + t * THREADS];
        }
        __syncthreads();
        #pragma unroll 4
        for (int kk = 0; kk < 32; kk++) {
            float2 f = *(const float2*)&featT[(kc + kk) * TILE_P + p0];
            const float4* wr = (const float4*)&wbuf[kk * D0 + og * 16];
            float wv[16];
            #pragma unroll
            for (int j = 0; j < 4; j++) *(float4*)&wv[j * 4] = wr[j];
            #pragma unroll
            for (int i = 0; i < 16; i++) {
                a0[i][0] += wv[i] * f.x;
                a0[i][1] += wv[i] * f.y;
            }
        }
    }

    // leaky relu -> y0T
    #pragma unroll
    for (int i = 0; i < 16; i++) {
        float v0 = a0[i][0]; v0 = (v0 > 0.f) ? v0 : 0.01f * v0;
        float v1 = a0[i][1]; v1 = (v1 > 0.f) ? v1 : 0.01f * v1;
        int o = og * 16 + i;
        *(float2*)&y0T[o * TILE_P + p0] = make_float2(v0, v1);
    }

    // ---------------- layer1: 64 outs, K=384 ([y0;feat]). Thread tile 8o x 2p ----------------
    float a1[8][2];
    #pragma unroll
    for (int i = 0; i < 8; i++) {
        float bv = __ldg(&b1[og * 8 + i]);
        a1[i][0] = bv; a1[i][1] = bv;
    }

    for (int kc = 0; kc < K1; kc += 64) {
        __syncthreads();   // first iter: also makes y0T visible
        {   // stage W1T chunk [64k][64o] = 4096 floats
            float4* dst = (float4*)wbuf;
            const float4* src = (const float4*)(g_W1T + kc * D1);
            #pragma unroll
            for (int t = 0; t < 4; t++) dst[tid + t * THREADS] = src[tid + t * THREADS];
        }
        __syncthreads();
        const float* srcT = (kc < D0) ? (y0T + kc * TILE_P) : (featT + (kc - D0) * TILE_P);
        #pragma unroll 4
        for (int kk = 0; kk < 64; kk++) {
            float2 f = *(const float2*)&srcT[kk * TILE_P + p0];
            const float4* wr = (const float4*)&wbuf[kk * D1 + og * 8];
            float wv[8];
            *(float4*)&wv[0] = wr[0];
            *(float4*)&wv[4] = wr[1];
            #pragma unroll
            for (int i = 0; i < 8; i++) {
                a1[i][0] += wv[i] * f.x;
                a1[i][1] += wv[i] * f.y;
            }
        }
    }

    __syncthreads();   // everyone done reading wbuf before it becomes y1T
    #pragma unroll
    for (int i = 0; i < 8; i++) {
        float v0 = a1[i][0]; v0 = (v0 > 0.f) ? v0 : 0.01f * v0;
        float v1 = a1[i][1]; v1 = (v1 > 0.f) ? v1 : 0.01f * v1;
        int o = og * 8 + i;
        *(float2*)&y1T[o * TILE_P + p0] = make_float2(v0, v1);
    }
    __syncthreads();

    // ---------------- layer2: 5 outs (padded 8), K=320 ([y1;feat]). o = og, 2 pts ----------------
    float c0a = (og < D2) ? __ldg(&b2[og]) : 0.f;
    float c1a = c0a;
    #pragma unroll 8
    for (int k = 0; k < D1; k++) {
        float wv = __ldg(&g_W2T[k * 8 + og]);       // warp-uniform address
        float2 f = *(const float2*)&y1T[k * TILE_P + p0];
        c0a += wv * f.x; c1a += wv * f.y;
    }
    #pragma unroll 8
    for (int k = 0; k < CC; k++) {
        float wv = __ldg(&g_W2T[(D1 + k) * 8 + og]);
        float2 f = *(const float2*)&featT[k * TILE_P + p0];
        c0a += wv * f.x; c1a += wv * f.y;
    }

    if (og < D2) {
        int n0 = tile * TILE_P + p0;
        float* ob = out + b * (D2 * NN) + og * NN;
        if (n0     < NN) ob[n0]     = fmaxf(c0a, 0.f);
        if (n0 + 1 < NN) ob[n0 + 1] = fmaxf(c1a, 0.f);
    }
}

extern "C" void kernel_launch(void* const* d_in, const int* in_sizes, int n_in,
                              void* d_out, int out_size) {
    const float* p   = (const float*)d_in[0];
    const float* cam = (const float*)d_in[1];
    const float* sf  = (const float*)d_in[2];
    const float* W0  = (const float*)d_in[3];
    const float* b0  = (const float*)d_in[4];
    const float* W1  = (const float*)d_in[5];
    const float* b1  = (const float*)d_in[6];
    const float* W2  = (const float*)d_in[7];
    const float* b2  = (const float*)d_in[8];
    float* out = (float*)d_out;

    prep_kernel<<<128, 256>>>(W0, W1, W2);

    cudaFuncSetAttribute(maf_fused, cudaFuncAttributeMaxDynamicSharedMemorySize, SMEM_BYTES);
    dim3 grid(NTILES, BB);
    maf_fused<<<grid, THREADS, SMEM_BYTES>>>(p, cam, sf, b0, b1, b2, out);
}

// round 3
// speedup vs baseline: 1.0319x; 1.0319x over previous
#include <cuda_runtime.h>
#include <cuda_fp16.h>
#include <math.h>

// Problem constants (fixed-shape problem)
#define BB 64
#define NN 431
#define CC 256
#define HH 56
#define WW 56
#define HW (HH*WW)            // 3136
#define D0 128
#define D1 64
#define D2 5
#define K1 (D0+CC)   // 384
#define K2 (D1+CC)   // 320
#define TILE_P 64
#define NTILES ((NN + TILE_P - 1) / TILE_P)  // 7
#define THREADS 256

// smem: featT[256][64] + y0T[128][64] + wbuf(4096 floats; params / weight staging / y1T)
#define SMEM_FLOATS ((CC + D0) * TILE_P + 4096)
#define SMEM_BYTES  (SMEM_FLOATS * 4)  // 114688 B -> 2 blocks/SM

// Scratch (__device__ globals per allocation rules)
__device__ float g_W0T[CC * D0];   // [k][o] 256x128
__device__ float g_W1T[K1 * D1];   // [k][o] 384x64
__device__ float g_W2T[K2 * 8];    // [k][o] 320x8 (o padded 5->8 with zeros)
__device__ __half g_sfT[(size_t)BB * HW * CC];  // (B, HW, C) fp16 feature map

__global__ void prep_kernel(const float* __restrict__ W0,
                            const float* __restrict__ W1,
                            const float* __restrict__ W2) {
    int i = blockIdx.x * blockDim.x + threadIdx.x;
    if (i < CC * D0) { int k = i / D0, o = i % D0; g_W0T[i] = W0[o * CC + k]; }
    if (i < K1 * D1) { int k = i / D1, o = i % D1; g_W1T[i] = W1[o * K1 + k]; }
    if (i < K2 * 8)  { int k = i / 8,  o = i % 8;  g_W2T[i] = (o < D2) ? W2[o * K2 + k] : 0.f; }
}

// (B,C,H,W) f32 -> (B,HW,C) f16. Tiled 32x32 transpose, coalesced both sides.
__global__ __launch_bounds__(256)
void transpose_kernel(const float* __restrict__ sf) {
    __shared__ float tile[32][33];
    const int b  = blockIdx.z;
    const int c0 = blockIdx.y * 32;
    const int p0 = blockIdx.x * 32;   // pixel (flat HW) tile; 3136 = 98*32 exact
    const int tx = threadIdx.x, ty = threadIdx.y;
    const float* src = sf + (size_t)b * CC * HW;
    #pragma unroll
    for (int j = 0; j < 4; j++)
        tile[ty * 4 + j][tx] = src[(size_t)(c0 + ty * 4 + j) * HW + p0 + tx];
    __syncthreads();
    __half* dst = g_sfT + (size_t)b * HW * CC;
    #pragma unroll
    for (int j = 0; j < 4; j++)
        dst[(size_t)(p0 + ty * 4 + j) * CC + c0 + tx] = __float2half(tile[tx][ty * 4 + j]);
}

__global__ __launch_bounds__(THREADS, 2)
void maf_fused(const float* __restrict__ p, const float* __restrict__ cam,
               const float* __restrict__ b0, const float* __restrict__ b1,
               const float* __restrict__ b2, float* __restrict__ out)
{
    extern __shared__ float smem[];
    float* featT = smem;                         // [CC][TILE_P]
    float* y0T   = smem + CC * TILE_P;           // [D0][TILE_P]
    float* wbuf  = smem + (CC + D0) * TILE_P;    // 4096 floats (params -> weights -> y1T)
    float* y1T   = wbuf;

    const int tile = blockIdx.x;
    const int b    = blockIdx.y;
    const int tid  = threadIdx.x;

    // ---------------- point params: weights + pixel offsets into smem ----------------
    float* pW   = wbuf;                 // [4][64]
    int*   pOff = (int*)(wbuf + 256);   // [4][64] pixel*CC offsets
    if (tid < TILE_P) {
        const int n = tile * TILE_P + tid;
        float w00 = 0.f, w10 = 0.f, w01 = 0.f, w11 = 0.f;
        int o00 = 0, o10 = 0, o01 = 0, o11 = 0;
        if (n < NN) {
            float s  = cam[b * 3 + 0];
            float tx = cam[b * 3 + 1];
            float ty = cam[b * 3 + 2];
            float gx = (s * (p[(b * NN + n) * 3 + 0] + tx) + 1.f) * (0.5f * (WW - 1));
            float gy = (s * (p[(b * NN + n) * 3 + 1] + ty) + 1.f) * (0.5f * (HH - 1));
            float x0f = floorf(gx), y0f = floorf(gy);
            float wx1 = gx - x0f, wy1 = gy - y0f;
            float wx0 = 1.f - wx1, wy0 = 1.f - wy1;
            if (!(x0f       >= 0.f && x0f       <= (float)(WW - 1))) wx0 = 0.f;
            if (!(x0f + 1.f >= 0.f && x0f + 1.f <= (float)(WW - 1))) wx1 = 0.f;
            if (!(y0f       >= 0.f && y0f       <= (float)(HH - 1))) wy0 = 0.f;
            if (!(y0f + 1.f >= 0.f && y0f + 1.f <= (float)(HH - 1))) wy1 = 0.f;
            int ix0 = (int)fminf(fmaxf(x0f,       0.f), (float)(WW - 1));
            int ix1 = (int)fminf(fmaxf(x0f + 1.f, 0.f), (float)(WW - 1));
            int iy0 = (int)fminf(fmaxf(y0f,       0.f), (float)(HH - 1));
            int iy1 = (int)fminf(fmaxf(y0f + 1.f, 0.f), (float)(HH - 1));
            o00 = (iy0 * WW + ix0) * CC;
            o10 = (iy0 * WW + ix1) * CC;
            o01 = (iy1 * WW + ix0) * CC;
            o11 = (iy1 * WW + ix1) * CC;
            w00 = wx0 * wy0; w10 = wx1 * wy0; w01 = wx0 * wy1; w11 = wx1 * wy1;
        }
        pW[0 * 64 + tid] = w00; pW[1 * 64 + tid] = w10;
        pW[2 * 64 + tid] = w01; pW[3 * 64 + tid] = w11;
        pOff[0 * 64 + tid] = o00; pOff[1 * 64 + tid] = o10;
        pOff[2 * 64 + tid] = o01; pOff[3 * 64 + tid] = o11;
    }
    __syncthreads();

    // ---------------- gather: coalesced fp16 loads from g_sfT ----------------
    // thread = 4 points x 16 channels. cg-pair lanes read adjacent 16B -> full sectors.
    {
        const int l  = tid & 31;
        const int w  = tid >> 5;
        const int q  = l & 15;
        const int cg = l >> 4;
        const int pbase = q * 4;
        const __half* sfTb = g_sfT + (size_t)b * HW * CC;

        #pragma unroll
        for (int f4 = 0; f4 < 2; f4++) {
            const int c = w * 32 + cg * 8 + f4 * 16;
            float vv[8][4];
            #pragma unroll
            for (int sp = 0; sp < 4; sp++) {
                const int pt = pbase + sp;
                const float w00 = pW[0 * 64 + pt], w10 = pW[1 * 64 + pt];
                const float w01 = pW[2 * 64 + pt], w11 = pW[3 * 64 + pt];
                const int o00 = pOff[0 * 64 + pt], o10 = pOff[1 * 64 + pt];
                const int o01 = pOff[2 * 64 + pt], o11 = pOff[3 * 64 + pt];
                uint4 A = *(const uint4*)(sfTb + o00 + c);
                uint4 Bv = *(const uint4*)(sfTb + o10 + c);
                uint4 Cv = *(const uint4*)(sfTb + o01 + c);
                uint4 Dv = *(const uint4*)(sfTb + o11 + c);
                const __half2* a2 = (const __half2*)&A;
                const __half2* b2h = (const __half2*)&Bv;
                const __half2* c2 = (const __half2*)&Cv;
                const __half2* d2 = (const __half2*)&Dv;
                #pragma unroll
                for (int k = 0; k < 4; k++) {
                    float2 fa = __half22float2(a2[k]);
                    float2 fb = __half22float2(b2h[k]);
                    float2 fc = __half22float2(c2[k]);
                    float2 fd = __half22float2(d2[k]);
                    vv[2 * k + 0][sp] = w00 * fa.x + w10 * fb.x + w01 * fc.x + w11 * fd.x;
                    vv[2 * k + 1][sp] = w00 * fa.y + w10 * fb.y + w01 * fc.y + w11 * fd.y;
                }
            }
            #pragma unroll
            for (int j = 0; j < 8; j++) {
                *(float4*)&featT[(c + j) * TILE_P + pbase] =
                    make_float4(vv[j][0], vv[j][1], vv[j][2], vv[j][3]);
            }
        }
    }

    const int og   = tid >> 5;     // warp id 0..7
    const int lane = tid & 31;
    const int p0i  = lane * 2;     // 2 points per thread

    // ---------------- layer0: 128 outs, K=256. Thread tile 16o x 2p ----------------
    float a0[16][2];
    #pragma unroll
    for (int i = 0; i < 16; i++) {
        float bv = __ldg(&b0[og * 16 + i]);
        a0[i][0] = bv; a0[i][1] = bv;
    }

    for (int kc = 0; kc < CC; kc += 32) {
        __syncthreads();   // first iter: gather done reading params / writing featT
        {   // stage W0T chunk [32k][128o] = 4096 floats (overwrites params region)
            float4* dst = (float4*)wbuf;
            const float4* src = (const float4*)(g_W0T + kc * D0);
            #pragma unroll
            for (int t = 0; t < 4; t++) dst[tid + t * THREADS] = src[tid + t * THREADS];
        }
        __syncthreads();
        #pragma unroll 4
        for (int kk = 0; kk < 32; kk++) {
            float2 f = *(const float2*)&featT[(kc + kk) * TILE_P + p0i];
            const float4* wr = (const float4*)&wbuf[kk * D0 + og * 16];
            float wv[16];
            #pragma unroll
            for (int j = 0; j < 4; j++) *(float4*)&wv[j * 4] = wr[j];
            #pragma unroll
            for (int i = 0; i < 16; i++) {
                a0[i][0] += wv[i] * f.x;
                a0[i][1] += wv[i] * f.y;
            }
        }
    }

    // leaky relu -> y0T
    #pragma unroll
    for (int i = 0; i < 16; i++) {
        float v0 = a0[i][0]; v0 = (v0 > 0.f) ? v0 : 0.01f * v0;
        float v1 = a0[i][1]; v1 = (v1 > 0.f) ? v1 : 0.01f * v1;
        int o = og * 16 + i;
        *(float2*)&y0T[o * TILE_P + p0i] = make_float2(v0, v1);
    }

    // ---------------- layer1: 64 outs, K=384 ([y0;feat]). Thread tile 8o x 2p ----------------
    float a1[8][2];
    #pragma unroll
    for (int i = 0; i < 8; i++) {
        float bv = __ldg(&b1[og * 8 + i]);
        a1[i][0] = bv; a1[i][1] = bv;
    }

    for (int kc = 0; kc < K1; kc += 64) {
        __syncthreads();   // first iter: y0T visible
        {   // stage W1T chunk [64k][64o] = 4096 floats
            float4* dst = (float4*)wbuf;
            const float4* src = (const float4*)(g_W1T + kc * D1);
            #pragma unroll
            for (int t = 0; t < 4; t++) dst[tid + t * THREADS] = src[tid + t * THREADS];
        }
        __syncthreads();
        const float* srcT = (kc < D0) ? (y0T + kc * TILE_P) : (featT + (kc - D0) * TILE_P);
        #pragma unroll 4
        for (int kk = 0; kk < 64; kk++) {
            float2 f = *(const float2*)&srcT[kk * TILE_P + p0i];
            const float4* wr = (const float4*)&wbuf[kk * D1 + og * 8];
            float wv[8];
            *(float4*)&wv[0] = wr[0];
            *(float4*)&wv[4] = wr[1];
            #pragma unroll
            for (int i = 0; i < 8; i++) {
                a1[i][0] += wv[i] * f.x;
                a1[i][1] += wv[i] * f.y;
            }
        }
    }

    __syncthreads();   // done reading wbuf before it becomes y1T
    #pragma unroll
    for (int i = 0; i < 8; i++) {
        float v0 = a1[i][0]; v0 = (v0 > 0.f) ? v0 : 0.01f * v0;
        float v1 = a1[i][1]; v1 = (v1 > 0.f) ? v1 : 0.01f * v1;
        int o = og * 8 + i;
        *(float2*)&y1T[o * TILE_P + p0i] = make_float2(v0, v1);
    }
    __syncthreads();

    // ---------------- layer2: 5 outs (padded 8), K=320 ([y1;feat]). o = og, 2 pts ----------------
    float c0a = (og < D2) ? __ldg(&b2[og]) : 0.f;
    float c1a = c0a;
    #pragma unroll 8
    for (int k = 0; k < D1; k++) {
        float wv = __ldg(&g_W2T[k * 8 + og]);       // warp-uniform address
        float2 f = *(const float2*)&y1T[k * TILE_P + p0i];
        c0a += wv * f.x; c1a += wv * f.y;
    }
    #pragma unroll 8
    for (int k = 0; k < CC; k++) {
        float wv = __ldg(&g_W2T[(D1 + k) * 8 + og]);
        float2 f = *(const float2*)&featT[k * TILE_P + p0i];
        c0a += wv * f.x; c1a += wv * f.y;
    }

    if (og < D2) {
        int n0 = tile * TILE_P + p0i;
        float* ob = out + b * (D2 * NN) + og * NN;
        if (n0     < NN) ob[n0]     = fmaxf(c0a, 0.f);
        if (n0 + 1 < NN) ob[n0 + 1] = fmaxf(c1a, 0.f);
    }
}

extern "C" void kernel_launch(void* const* d_in, const int* in_sizes, int n_in,
                              void* d_out, int out_size) {
    const float* p   = (const float*)d_in[0];
    const float* cam = (const float*)d_in[1];
    const float* sf  = (const float*)d_in[2];
    const float* W0  = (const float*)d_in[3];
    const float* b0  = (const float*)d_in[4];
    const float* W1  = (const float*)d_in[5];
    const float* b1  = (const float*)d_in[6];
    const float* W2  = (const float*)d_in[7];
    const float* b2  = (const float*)d_in[8];
    float* out = (float*)d_out;

    prep_kernel<<<128, 256>>>(W0, W1, W2);

    dim3 tgrid(HW / 32, CC / 32, BB);   // (98, 8, 64)
    transpose_kernel<<<tgrid, dim3(32, 8)>>>(sf);

    cudaFuncSetAttribute(maf_fused, cudaFuncAttributeMaxDynamicSharedMemorySize, SMEM_BYTES);
    dim3 grid(NTILES, BB);
    maf_fused<<<grid, THREADS, SMEM_BYTES>>>(p, cam, b0, b1, b2, out);
}

// round 5
// speedup vs baseline: 1.4862x; 1.4404x over previous
#include <cuda_runtime.h>
#include <cuda_fp16.h>
#include <math.h>

typedef unsigned long long ull;

// Problem constants (fixed-shape problem)
#define BB 64
#define NN 431
#define CC 256
#define HH 56
#define WW 56
#define HW (HH*WW)            // 3136
#define D0 128
#define D1 64
#define D2 5
#define K1 (D0+CC)   // 384
#define K2 (D1+CC)   // 320
#define TILE_P 64
#define NPTS (BB*NN)                 // 27584
#define NTILES (NPTS / TILE_P)       // 431 exactly, zero padding
#define THREADS 512

// smem: featT[256][64] + y0T[128][64] + wbuf(4096 floats; params / weight staging / y1T)
#define SMEM_FLOATS ((CC + D0) * TILE_P + 4096)
#define SMEM_BYTES  (SMEM_FLOATS * 4)  // 114688 B -> 2 blocks/SM

// Scratch (__device__ globals per allocation rules)
__device__ float g_W0T[CC * D0];   // [k][o] 256x128
__device__ float g_W1T[K1 * D1];   // [k][o] 384x64
__device__ float g_W2T[K2 * 8];    // [k][o] 320x8 (o padded 5->8 with zeros)
__device__ __half g_sfT[(size_t)BB * HW * CC];  // (B, HW, C) fp16 feature map

__device__ __forceinline__ void ffma2(ull& acc, ull a, ull b) {
    asm("fma.rn.f32x2 %0, %1, %2, %0;" : "+l"(acc) : "l"(a), "l"(b));
}
__device__ __forceinline__ ull pack2(float x, float y) {
    ull r;
    asm("mov.b64 %0, {%1, %2};" : "=l"(r) : "r"(__float_as_uint(x)), "r"(__float_as_uint(y)));
    return r;
}
__device__ __forceinline__ ull dup2(float x) {
    ull r;
    asm("mov.b64 %0, {%1, %1};" : "=l"(r) : "r"(__float_as_uint(x)));
    return r;
}
__device__ __forceinline__ float2 unpack2(ull v) {
    unsigned lo, hi;
    asm("mov.b64 {%0, %1}, %2;" : "=r"(lo), "=r"(hi) : "l"(v));
    return make_float2(__uint_as_float(lo), __uint_as_float(hi));
}

__global__ void prep_kernel(const float* __restrict__ W0,
                            const float* __restrict__ W1,
                            const float* __restrict__ W2) {
    int i = blockIdx.x * blockDim.x + threadIdx.x;
    if (i < CC * D0) { int k = i / D0, o = i % D0; g_W0T[i] = W0[o * CC + k]; }
    if (i < K1 * D1) { int k = i / D1, o = i % D1; g_W1T[i] = W1[o * K1 + k]; }
    if (i < K2 * 8)  { int k = i / 8,  o = i % 8;  g_W2T[i] = (o < D2) ? W2[o * K2 + k] : 0.f; }
}

// (B,C,H,W) f32 -> (B,HW,C) f16. Tiled 32x32 transpose.
// Store phase: 512 items (32 pixel rows x 16 half2) over 256 threads; channel
// index stays < 32 (fixes R4's OOB tile[2*tx] read).
__global__ __launch_bounds__(256)
void transpose_kernel(const float* __restrict__ sf) {
    __shared__ float tile[32][33];
    const int b  = blockIdx.z;
    const int c0 = blockIdx.y * 32;
    const int p0 = blockIdx.x * 32;   // 3136 = 98*32 exact
    const int tx = threadIdx.x, ty = threadIdx.y;
    const float* src = sf + (size_t)b * CC * HW;
    #pragma unroll
    for (int j = 0; j < 4; j++)
        tile[ty * 4 + j][tx] = src[(size_t)(c0 + ty * 4 + j) * HW + p0 + tx];
    __syncthreads();
    __half2* dst = (__half2*)(g_sfT + (size_t)b * HW * CC);
    const int t = ty * 32 + tx;       // 0..255
    #pragma unroll
    for (int it = 0; it < 2; it++) {
        int item = t + it * 256;      // 0..511
        int pr   = item >> 4;         // pixel row 0..31
        int ch2  = item & 15;         // half2 index 0..15 -> channels 2*ch2, 2*ch2+1 (<32)
        __half2 v = __floats2half2_rn(tile[2 * ch2][pr], tile[2 * ch2 + 1][pr]);
        dst[((size_t)(p0 + pr) * CC + c0) / 2 + ch2] = v;
    }
}

__global__ __launch_bounds__(THREADS, 2)
void maf_fused(const float* __restrict__ p, const float* __restrict__ cam,
               const float* __restrict__ b0, const float* __restrict__ b1,
               const float* __restrict__ b2, float* __restrict__ out)
{
    extern __shared__ float smem[];
    float* featT = smem;                         // [CC][TILE_P]
    float* y0T   = smem + CC * TILE_P;           // [D0][TILE_P]
    float* wbuf  = smem + (CC + D0) * TILE_P;    // 4096 floats (params -> weights -> y1T)
    float* y1T   = wbuf;

    const int tile = blockIdx.x;
    const int tid  = threadIdx.x;

    // ---------------- point params (weights + offsets) into wbuf ----------------
    float* pW   = wbuf;                 // [4][64]
    int*   pOff = (int*)(wbuf + 256);   // [4][64] element offsets into g_sfT (b folded in)
    if (tid < TILE_P) {
        const int gp = tile * TILE_P + tid;     // global point, always valid (27584 = 431*64)
        const int b  = gp / NN;
        float s  = cam[b * 3 + 0];
        float tx = cam[b * 3 + 1];
        float ty = cam[b * 3 + 2];
        float gx = (s * (p[gp * 3 + 0] + tx) + 1.f) * (0.5f * (WW - 1));
        float gy = (s * (p[gp * 3 + 1] + ty) + 1.f) * (0.5f * (HH - 1));
        float x0f = floorf(gx), y0f = floorf(gy);
        float wx1 = gx - x0f, wy1 = gy - y0f;
        float wx0 = 1.f - wx1, wy0 = 1.f - wy1;
        if (!(x0f       >= 0.f && x0f       <= (float)(WW - 1))) wx0 = 0.f;
        if (!(x0f + 1.f >= 0.f && x0f + 1.f <= (float)(WW - 1))) wx1 = 0.f;
        if (!(y0f       >= 0.f && y0f       <= (float)(HH - 1))) wy0 = 0.f;
        if (!(y0f + 1.f >= 0.f && y0f + 1.f <= (float)(HH - 1))) wy1 = 0.f;
        int ix0 = (int)fminf(fmaxf(x0f,       0.f), (float)(WW - 1));
        int ix1 = (int)fminf(fmaxf(x0f + 1.f, 0.f), (float)(WW - 1));
        int iy0 = (int)fminf(fmaxf(y0f,       0.f), (float)(HH - 1));
        int iy1 = (int)fminf(fmaxf(y0f + 1.f, 0.f), (float)(HH - 1));
        int base = b * HW;
        pOff[0 * 64 + tid] = (base + iy0 * WW + ix0) * CC;
        pOff[1 * 64 + tid] = (base + iy0 * WW + ix1) * CC;
        pOff[2 * 64 + tid] = (base + iy1 * WW + ix0) * CC;
        pOff[3 * 64 + tid] = (base + iy1 * WW + ix1) * CC;
        pW[0 * 64 + tid] = wx0 * wy0; pW[1 * 64 + tid] = wx1 * wy0;
        pW[2 * 64 + tid] = wx0 * wy1; pW[3 * 64 + tid] = wx1 * wy1;
    }
    __syncthreads();

    // ---------------- gather: coalesced fp16 loads ----------------
    // thread = 4 points x 8 channels; warp covers 16 channels x 64 points.
    {
        const int l  = tid & 31;
        const int w  = tid >> 5;          // 0..15
        const int q  = l & 15;
        const int cg = l >> 4;
        const int pbase = q * 4;
        const int c = w * 16 + cg * 8;

        float vv[8][4];
        #pragma unroll
        for (int sp = 0; sp < 4; sp++) {
            const int pt = pbase + sp;
            const float w00 = pW[0 * 64 + pt], w10 = pW[1 * 64 + pt];
            const float w01 = pW[2 * 64 + pt], w11 = pW[3 * 64 + pt];
            const int o00 = pOff[0 * 64 + pt], o10 = pOff[1 * 64 + pt];
            const int o01 = pOff[2 * 64 + pt], o11 = pOff[3 * 64 + pt];
            uint4 A  = *(const uint4*)(g_sfT + o00 + c);
            uint4 Bv = *(const uint4*)(g_sfT + o10 + c);
            uint4 Cv = *(const uint4*)(g_sfT + o01 + c);
            uint4 Dv = *(const uint4*)(g_sfT + o11 + c);
            const __half2* a2 = (const __half2*)&A;
            const __half2* b2h = (const __half2*)&Bv;
            const __half2* c2 = (const __half2*)&Cv;
            const __half2* d2 = (const __half2*)&Dv;
            #pragma unroll
            for (int k = 0; k < 4; k++) {
                float2 fa = __half22float2(a2[k]);
                float2 fb = __half22float2(b2h[k]);
                float2 fc = __half22float2(c2[k]);
                float2 fd = __half22float2(d2[k]);
                vv[2 * k + 0][sp] = w00 * fa.x + w10 * fb.x + w01 * fc.x + w11 * fd.x;
                vv[2 * k + 1][sp] = w00 * fa.y + w10 * fb.y + w01 * fc.y + w11 * fd.y;
            }
        }
        #pragma unroll
        for (int j = 0; j < 8; j++)
            *(float4*)&featT[(c + j) * TILE_P + pbase] =
                make_float4(vv[j][0], vv[j][1], vv[j][2], vv[j][3]);
    }

    const int pt = tid & 63;       // point within tile
    const int og = tid >> 6;       // output group 0..7 (warp-uniform)

    // ---------------- layer0: 128 outs, K=256. Thread = 1pt x 16 outs (8 f32x2 pairs) ----------------
    ull a0[8];
    #pragma unroll
    for (int j = 0; j < 8; j++)
        a0[j] = pack2(__ldg(&b0[og * 16 + 2 * j]), __ldg(&b0[og * 16 + 2 * j + 1]));

    for (int kc = 0; kc < CC; kc += 32) {
        __syncthreads();   // first iter: gather done (params read, featT written)
        {   // stage W0T chunk [32k][128o] = 4096 floats
            float4* dst = (float4*)wbuf;
            const float4* src = (const float4*)(g_W0T + kc * D0);
            dst[tid]       = src[tid];
            dst[tid + 512] = src[tid + 512];
        }
        __syncthreads();
        #pragma unroll 8
        for (int kk = 0; kk < 32; kk++) {
            ull ff = dup2(featT[(kc + kk) * TILE_P + pt]);
            const ull* wr = (const ull*)&wbuf[kk * D0 + og * 16];   // warp-uniform, 16B-aligned
            #pragma unroll
            for (int j = 0; j < 8; j++) ffma2(a0[j], ff, wr[j]);
        }
    }

    // leaky relu -> y0T
    #pragma unroll
    for (int j = 0; j < 8; j++) {
        float2 v = unpack2(a0[j]);
        v.x = (v.x > 0.f) ? v.x : 0.01f * v.x;
        v.y = (v.y > 0.f) ? v.y : 0.01f * v.y;
        y0T[(og * 16 + 2 * j)     * TILE_P + pt] = v.x;
        y0T[(og * 16 + 2 * j + 1) * TILE_P + pt] = v.y;
    }

    // ---------------- layer1: 64 outs, K=384 ([y0;feat]). Thread = 1pt x 8 outs ----------------
    ull a1[4];
    #pragma unroll
    for (int j = 0; j < 4; j++)
        a1[j] = pack2(__ldg(&b1[og * 8 + 2 * j]), __ldg(&b1[og * 8 + 2 * j + 1]));

    for (int kc = 0; kc < K1; kc += 64) {
        __syncthreads();   // first iter: y0T visible
        {   // stage W1T chunk [64k][64o] = 4096 floats
            float4* dst = (float4*)wbuf;
            const float4* src = (const float4*)(g_W1T + kc * D1);
            dst[tid]       = src[tid];
            dst[tid + 512] = src[tid + 512];
        }
        __syncthreads();
        const float* srcT = (kc < D0) ? (y0T + kc * TILE_P) : (featT + (kc - D0) * TILE_P);
        #pragma unroll 8
        for (int kk = 0; kk < 64; kk++) {
            ull ff = dup2(srcT[kk * TILE_P + pt]);
            const ull* wr = (const ull*)&wbuf[kk * D1 + og * 8];
            #pragma unroll
            for (int j = 0; j < 4; j++) ffma2(a1[j], ff, wr[j]);
        }
    }

    __syncthreads();   // done reading wbuf before it becomes y1T
    #pragma unroll
    for (int j = 0; j < 4; j++) {
        float2 v = unpack2(a1[j]);
        v.x = (v.x > 0.f) ? v.x : 0.01f * v.x;
        v.y = (v.y > 0.f) ? v.y : 0.01f * v.y;
        y1T[(og * 8 + 2 * j)     * TILE_P + pt] = v.x;
        y1T[(og * 8 + 2 * j + 1) * TILE_P + pt] = v.y;
    }
    __syncthreads();

    // ---------------- layer2: 5 outs (padded 8), K=320 ([y1;feat]). Thread = 1pt x 1 out ----------------
    float acc = (og < D2) ? __ldg(&b2[og]) : 0.f;
    #pragma unroll 8
    for (int k = 0; k < D1; k++) {
        float wv = __ldg(&g_W2T[k * 8 + og]);          // warp-uniform
        acc += wv * y1T[k * TILE_P + pt];
    }
    #pragma unroll 8
    for (int k = 0; k < CC; k++) {
        float wv = __ldg(&g_W2T[(D1 + k) * 8 + og]);
        acc += wv * featT[k * TILE_P + pt];
    }

    if (og < D2) {
        int gp = tile * TILE_P + pt;
        int b  = gp / NN;
        int n  = gp - b * NN;
        out[b * (D2 * NN) + og * NN + n] = fmaxf(acc, 0.f);
    }
}

extern "C" void kernel_launch(void* const* d_in, const int* in_sizes, int n_in,
                              void* d_out, int out_size) {
    const float* p   = (const float*)d_in[0];
    const float* cam = (const float*)d_in[1];
    const float* sf  = (const float*)d_in[2];
    const float* W0  = (const float*)d_in[3];
    const float* b0  = (const float*)d_in[4];
    const float* W1  = (const float*)d_in[5];
    const float* b1  = (const float*)d_in[6];
    const float* W2  = (const float*)d_in[7];
    const float* b2  = (const float*)d_in[8];
    float* out = (float*)d_out;

    prep_kernel<<<128, 256>>>(W0, W1, W2);

    dim3 tgrid(HW / 32, CC / 32, BB);   // (98, 8, 64)
    transpose_kernel<<<tgrid, dim3(32, 8)>>>(sf);

    cudaFuncSetAttribute(maf_fused, cudaFuncAttributeMaxDynamicSharedMemorySize, SMEM_BYTES);
    maf_fused<<<NTILES, THREADS, SMEM_BYTES>>>(p, cam, b0, b1, b2, out);
}

// round 7
// speedup vs baseline: 1.5592x; 1.0491x over previous
#include <cuda_runtime.h>
#include <cuda_fp16.h>
#include <math.h>

typedef unsigned long long ull;

// Problem constants (fixed-shape problem)
#define BB 64
#define NN 431
#define CC 256
#define HH 56
#define WW 56
#define HW (HH*WW)            // 3136
#define D0 128
#define D1 64
#define D2 5
#define K1 (D0+CC)   // 384
#define K2 (D1+CC)   // 320
#define TILE_P 64
#define NPTS (BB*NN)                 // 27584
#define NTILES (NPTS / TILE_P)       // 431 exactly
#define THREADS 512

// smem: featT[256][64] + y0T[128][64] + wbuf(4096 floats: params / 2x8KB weight double-buffer / y1T)
#define SMEM_FLOATS ((CC + D0) * TILE_P + 4096)
#define SMEM_BYTES  (SMEM_FLOATS * 4)  // 114688 B -> 2 blocks/SM

// Scratch (__device__ globals per allocation rules)
__device__ float g_W0T[CC * D0];   // [k][o] 256x128
__device__ float g_W1T[K1 * D1];   // [k][o] 384x64
__device__ float g_W2T[K2 * 8];    // [k][o] 320x8 (o padded 5->8 with zeros)
__device__ __half g_sfT[(size_t)BB * HW * CC];  // (B, HW, C) fp16 feature map

__device__ __forceinline__ void ffma2(ull& acc, ull a, ull b) {
    asm("fma.rn.f32x2 %0, %1, %2, %0;" : "+l"(acc) : "l"(a), "l"(b));
}
__device__ __forceinline__ ull pack2(float x, float y) {
    ull r;
    asm("mov.b64 %0, {%1, %2};" : "=l"(r) : "r"(__float_as_uint(x)), "r"(__float_as_uint(y)));
    return r;
}
__device__ __forceinline__ ull dup2(float x) {
    ull r;
    asm("mov.b64 %0, {%1, %1};" : "=l"(r) : "r"(__float_as_uint(x)));
    return r;
}
__device__ __forceinline__ float2 unpack2(ull v) {
    unsigned lo, hi;
    asm("mov.b64 {%0, %1}, %2;" : "=r"(lo), "=r"(hi) : "l"(v));
    return make_float2(__uint_as_float(lo), __uint_as_float(hi));
}
__device__ __forceinline__ void cp_async16(float* smem_dst, const float* gsrc) {
    unsigned sa = (unsigned)__cvta_generic_to_shared(smem_dst);
    asm volatile("cp.async.cg.shared.global [%0], [%1], 16;" :: "r"(sa), "l"(gsrc));
}
__device__ __forceinline__ void cp_commit() { asm volatile("cp.async.commit_group;"); }
__device__ __forceinline__ void cp_wait1() { asm volatile("cp.async.wait_group 1;"); }
__device__ __forceinline__ void cp_wait0() { asm volatile("cp.async.wait_group 0;"); }

// (B,C,H,W) f32 -> (B,HW,C) f16 transpose. First 234 flat blocks also build the
// transposed weight tables (59904 = 234*256 elements, exact).
__global__ __launch_bounds__(256)
void transpose_kernel(const float* __restrict__ sf,
                      const float* __restrict__ W0,
                      const float* __restrict__ W1,
                      const float* __restrict__ W2) {
    __shared__ float tile[32][33];
    const int b  = blockIdx.z;
    const int c0 = blockIdx.y * 32;
    const int p0 = blockIdx.x * 32;   // 3136 = 98*32 exact
    const int tx = threadIdx.x, ty = threadIdx.y;
    const int t  = ty * 32 + tx;

    // weight prep (spread over first 234 flat blocks)
    {
        int fb = (blockIdx.z * 8 + blockIdx.y) * 98 + blockIdx.x;
        if (fb < 234) {
            int i = fb * 256 + t;
            if (i < CC * D0) {
                int k = i / D0, o = i % D0; g_W0T[i] = W0[o * CC + k];
            } else if (i < CC * D0 + K1 * D1) {
                int j = i - CC * D0;
                int k = j / D1, o = j % D1; g_W1T[j] = W1[o * K1 + k];
            } else {
                int j = i - CC * D0 - K1 * D1;   // < 2560
                int k = j / 8, o = j % 8; g_W2T[j] = (o < D2) ? W2[o * K2 + k] : 0.f;
            }
        }
    }

    const float* src = sf + (size_t)b * CC * HW;
    #pragma unroll
    for (int j = 0; j < 4; j++)
        tile[ty * 4 + j][tx] = src[(size_t)(c0 + ty * 4 + j) * HW + p0 + tx];
    __syncthreads();
    // store: 256 items of 8B (4 channels x 1 pixel row each)
    const int pr  = t >> 3;        // pixel row 0..31
    const int ch4 = t & 7;         // 4-channel group 0..7
    __half2 v0 = __floats2half2_rn(tile[4 * ch4 + 0][pr], tile[4 * ch4 + 1][pr]);
    __half2 v1 = __floats2half2_rn(tile[4 * ch4 + 2][pr], tile[4 * ch4 + 3][pr]);
    uint2 pkt = make_uint2(*(unsigned*)&v0, *(unsigned*)&v1);
    uint2* dst = (uint2*)(g_sfT + (size_t)b * HW * CC + (size_t)(p0 + pr) * CC + c0);
    dst[ch4] = pkt;
}

__global__ __launch_bounds__(THREADS, 2)
void maf_fused(const float* __restrict__ p, const float* __restrict__ cam,
               const float* __restrict__ b0, const float* __restrict__ b1,
               const float* __restrict__ b2, float* __restrict__ out)
{
    extern __shared__ float smem[];
    float* featT = smem;                         // [CC][TILE_P]
    float* y0T   = smem + CC * TILE_P;           // [D0][TILE_P]
    float* wbuf  = smem + (CC + D0) * TILE_P;    // 4096 floats
    float* bufA  = wbuf;                         // 2048 floats (8KB)
    float* bufB  = wbuf + 2048;
    float* y1T   = wbuf;                         // after layer1

    const int tile = blockIdx.x;
    const int tid  = threadIdx.x;

    // ---------------- point params (weights + offsets) into wbuf ----------------
    float* pW   = wbuf;                 // [4][64]
    int*   pOff = (int*)(wbuf + 256);   // [4][64]
    if (tid < TILE_P) {
        const int gp = tile * TILE_P + tid;     // always valid (27584 = 431*64)
        const int b  = gp / NN;
        float s  = cam[b * 3 + 0];
        float tx = cam[b * 3 + 1];
        float ty = cam[b * 3 + 2];
        float gx = (s * (p[gp * 3 + 0] + tx) + 1.f) * (0.5f * (WW - 1));
        float gy = (s * (p[gp * 3 + 1] + ty) + 1.f) * (0.5f * (HH - 1));
        float x0f = floorf(gx), y0f = floorf(gy);
        float wx1 = gx - x0f, wy1 = gy - y0f;
        float wx0 = 1.f - wx1, wy0 = 1.f - wy1;
        if (!(x0f       >= 0.f && x0f       <= (float)(WW - 1))) wx0 = 0.f;
        if (!(x0f + 1.f >= 0.f && x0f + 1.f <= (float)(WW - 1))) wx1 = 0.f;
        if (!(y0f       >= 0.f && y0f       <= (float)(HH - 1))) wy0 = 0.f;
        if (!(y0f + 1.f >= 0.f && y0f + 1.f <= (float)(HH - 1))) wy1 = 0.f;
        int ix0 = (int)fminf(fmaxf(x0f,       0.f), (float)(WW - 1));
        int ix1 = (int)fminf(fmaxf(x0f + 1.f, 0.f), (float)(WW - 1));
        int iy0 = (int)fminf(fmaxf(y0f,       0.f), (float)(HH - 1));
        int iy1 = (int)fminf(fmaxf(y0f + 1.f, 0.f), (float)(HH - 1));
        int base = b * HW;
        pOff[0 * 64 + tid] = (base + iy0 * WW + ix0) * CC;
        pOff[1 * 64 + tid] = (base + iy0 * WW + ix1) * CC;
        pOff[2 * 64 + tid] = (base + iy1 * WW + ix0) * CC;
        pOff[3 * 64 + tid] = (base + iy1 * WW + ix1) * CC;
        pW[0 * 64 + tid] = wx0 * wy0; pW[1 * 64 + tid] = wx1 * wy0;
        pW[2 * 64 + tid] = wx0 * wy1; pW[3 * 64 + tid] = wx1 * wy1;
    }
    __syncthreads();

    // ---------------- gather: coalesced fp16 loads ----------------
    {
        const int l  = tid & 31;
        const int w  = tid >> 5;          // 0..15
        const int q  = l & 15;
        const int cg = l >> 4;
        const int pbase = q * 4;
        const int c = w * 16 + cg * 8;

        float vv[8][4];
        #pragma unroll
        for (int sp = 0; sp < 4; sp++) {
            const int pt = pbase + sp;
            const float w00 = pW[0 * 64 + pt], w10 = pW[1 * 64 + pt];
            const float w01 = pW[2 * 64 + pt], w11 = pW[3 * 64 + pt];
            const int o00 = pOff[0 * 64 + pt], o10 = pOff[1 * 64 + pt];
            const int o01 = pOff[2 * 64 + pt], o11 = pOff[3 * 64 + pt];
            uint4 A  = *(const uint4*)(g_sfT + o00 + c);
            uint4 Bv = *(const uint4*)(g_sfT + o10 + c);
            uint4 Cv = *(const uint4*)(g_sfT + o01 + c);
            uint4 Dv = *(const uint4*)(g_sfT + o11 + c);
            const __half2* a2 = (const __half2*)&A;
            const __half2* b2h = (const __half2*)&Bv;
            const __half2* c2 = (const __half2*)&Cv;
            const __half2* d2 = (const __half2*)&Dv;
            #pragma unroll
            for (int k = 0; k < 4; k++) {
                float2 fa = __half22float2(a2[k]);
                float2 fb = __half22float2(b2h[k]);
                float2 fc = __half22float2(c2[k]);
                float2 fd = __half22float2(d2[k]);
                vv[2 * k + 0][sp] = w00 * fa.x + w10 * fb.x + w01 * fc.x + w11 * fd.x;
                vv[2 * k + 1][sp] = w00 * fa.y + w10 * fb.y + w01 * fc.y + w11 * fd.y;
            }
        }
        #pragma unroll
        for (int j = 0; j < 8; j++)
            *(float4*)&featT[(c + j) * TILE_P + pbase] =
                make_float4(vv[j][0], vv[j][1], vv[j][2], vv[j][3]);
    }

    const int pt = tid & 63;       // point within tile
    const int og = tid >> 6;       // output group 0..7 (warp-uniform)

    // ---------------- layer0: 128 outs, K=256; 16 chunks of 16k, double-buffered ----------------
    ull a0[8];
    #pragma unroll
    for (int j = 0; j < 8; j++)
        a0[j] = pack2(__ldg(&b0[og * 16 + 2 * j]), __ldg(&b0[og * 16 + 2 * j + 1]));

    __syncthreads();   // gather done: params consumed, featT written
    cp_async16(bufA + tid * 4, g_W0T + tid * 4);   // chunk 0
    cp_commit();

    #define NC0 16
    for (int c = 0; c < NC0; c++) {
        __syncthreads();   // all done computing chunk c-1 -> safe to overwrite buf[(c+1)&1]
        float* cur = (c & 1) ? bufB : bufA;
        if (c + 1 < NC0) {
            float* nxt = (c & 1) ? bufA : bufB;
            cp_async16(nxt + tid * 4, g_W0T + (c + 1) * 2048 + tid * 4);
            cp_commit();
            cp_wait1();
        } else {
            cp_wait0();
        }
        __syncthreads();   // chunk c visible to all
        const int kb = c * 16;
        #pragma unroll
        for (int kk = 0; kk < 16; kk++) {
            ull ff = dup2(featT[(kb + kk) * TILE_P + pt]);
            const ull* wr = (const ull*)&cur[kk * D0 + og * 16];
            #pragma unroll
            for (int j = 0; j < 8; j++) ffma2(a0[j], ff, wr[j]);
        }
    }

    // leaky relu -> y0T
    #pragma unroll
    for (int j = 0; j < 8; j++) {
        float2 v = unpack2(a0[j]);
        v.x = (v.x > 0.f) ? v.x : 0.01f * v.x;
        v.y = (v.y > 0.f) ? v.y : 0.01f * v.y;
        y0T[(og * 16 + 2 * j)     * TILE_P + pt] = v.x;
        y0T[(og * 16 + 2 * j + 1) * TILE_P + pt] = v.y;
    }

    // ---------------- layer1: 64 outs, K=384; 12 chunks of 32k, double-buffered ----------------
    ull a1[4];
    #pragma unroll
    for (int j = 0; j < 4; j++)
        a1[j] = pack2(__ldg(&b1[og * 8 + 2 * j]), __ldg(&b1[og * 8 + 2 * j + 1]));

    __syncthreads();   // layer0 fully done (y0T written, bufs free)
    cp_async16(bufA + tid * 4, g_W1T + tid * 4);   // chunk 0
    cp_commit();

    #define NC1 12
    for (int c = 0; c < NC1; c++) {
        __syncthreads();
        float* cur = (c & 1) ? bufB : bufA;
        if (c + 1 < NC1) {
            float* nxt = (c & 1) ? bufA : bufB;
            cp_async16(nxt + tid * 4, g_W1T + (c + 1) * 2048 + tid * 4);
            cp_commit();
            cp_wait1();
        } else {
            cp_wait0();
        }
        __syncthreads();
        const int kb = c * 32;
        const float* srcT = (kb < D0) ? (y0T + kb * TILE_P) : (featT + (kb - D0) * TILE_P);
        #pragma unroll 8
        for (int kk = 0; kk < 32; kk++) {
            ull ff = dup2(srcT[kk * TILE_P + pt]);
            const ull* wr = (const ull*)&cur[kk * D1 + og * 8];
            #pragma unroll
            for (int j = 0; j < 4; j++) ffma2(a1[j], ff, wr[j]);
        }
    }

    __syncthreads();   // done reading wbuf before it becomes y1T
    #pragma unroll
    for (int j = 0; j < 4; j++) {
        float2 v = unpack2(a1[j]);
        v.x = (v.x > 0.f) ? v.x : 0.01f * v.x;
        v.y = (v.y > 0.f) ? v.y : 0.01f * v.y;
        y1T[(og * 8 + 2 * j)     * TILE_P + pt] = v.x;
        y1T[(og * 8 + 2 * j + 1) * TILE_P + pt] = v.y;
    }
    __syncthreads();

    // ---------------- layer2: 5 outs (padded 8), K=320 ----------------
    float acc = (og < D2) ? __ldg(&b2[og]) : 0.f;
    #pragma unroll 8
    for (int k = 0; k < D1; k++) {
        float wv = __ldg(&g_W2T[k * 8 + og]);          // warp-uniform
        acc += wv * y1T[k * TILE_P + pt];
    }
    #pragma unroll 8
    for (int k = 0; k < CC; k++) {
        float wv = __ldg(&g_W2T[(D1 + k) * 8 + og]);
        acc += wv * featT[k * TILE_P + pt];
    }

    if (og < D2) {
        int gp = tile * TILE_P + pt;
        int b  = gp / NN;
        int n  = gp - b * NN;
        out[b * (D2 * NN) + og * NN + n] = fmaxf(acc, 0.f);
    }
}

extern "C" void kernel_launch(void* const* d_in, const int* in_sizes, int n_in,
                              void* d_out, int out_size) {
    const float* p   = (const float*)d_in[0];
    const float* cam = (const float*)d_in[1];
    const float* sf  = (const float*)d_in[2];
    const float* W0  = (const float*)d_in[3];
    const float* b0  = (const float*)d_in[4];
    const float* W1  = (const float*)d_in[5];
    const float* b1  = (const float*)d_in[6];
    const float* W2  = (const float*)d_in[7];
    const float* b2  = (const float*)d_in[8];
    float* out = (float*)d_out;

    dim3 tgrid(HW / 32, CC / 32, BB);   // (98, 8, 64)
    transpose_kernel<<<tgrid, dim3(32, 8)>>>(sf, W0, W1, W2);

    cudaFuncSetAttribute(maf_fused, cudaFuncAttributeMaxDynamicSharedMemorySize, SMEM_BYTES);
    maf_fused<<<NTILES, THREADS, SMEM_BYTES>>>(p, cam, b0, b1, b2, out);
}

// round 9
// speedup vs baseline: 3.5871x; 2.3007x over previous
#include <cuda_runtime.h>
#include <cuda_fp16.h>
#include <math.h>

// ---------------- problem constants ----------------
#define BB 64
#define NN 431
#define CC 256
#define HH 56
#define WW 56
#define HW (HH*WW)            // 3136
#define NPTS (BB*NN)          // 27584
#define TILE_P 128
#define NTILES ((NPTS + TILE_P - 1) / TILE_P)   // 216
#define THREADS 256

// ---------------- smem map (byte offsets) ----------------
#define SM_PRM  0                        // 4KB: pW f32[4][128] + pOff s32[4][128]
#define SM_FEAT 4096                     // feat [128 r][256 k] fp16, stride 512B, swz (64KB)
#define SM_Y0   (SM_FEAT + 65536)        // y0 [128][128] fp16, stride 256B (32KB)
#define SM_BUF  (SM_Y0 + 32768)          // 64KB: W0 [128][256] during L0; then W1 [64][384] (48KB) + y1
#define SM_Y1   (SM_BUF + 49152)         // y1 [128][64] fp16, stride 128B (16KB)
#define SM_W2   (SM_BUF + 65536)         // W2 [8][320] fp16, stride 640B (5KB)
#define SM_TOTAL (SM_W2 + 5120)          // 173056 B -> 1 block/SM

// ---------------- global scratch ----------------
__device__ __align__(16) unsigned char g_W0s[128*256*2];   // swizzled fp16 [o][k]
__device__ __align__(16) unsigned char g_W1s[64*384*2];
__device__ __align__(16) unsigned char g_W2s[8*320*2];     // rows 5..7 zero
__device__ __half g_sfT[(size_t)BB * HW * CC];             // (B, HW, C) fp16

// ---------------- helpers ----------------
// byte offset of (row r, fp16 col k) in a K-major tile with row stride S bytes.
// XOR swizzle on 16B columns within aligned groups of 8 -> conflict-free ldmatrix.
__device__ __forceinline__ int tile_off(int r, int k, int S) {
    int c16 = k >> 3;
    return r * S + ((((c16 & ~7) | ((c16 ^ r) & 7))) << 4) + ((k & 7) << 1);
}
__device__ __forceinline__ unsigned smem_u32(const void* p) {
    unsigned a;
    asm("{ .reg .u64 t; cvta.to.shared.u64 t, %1; cvt.u32.u64 %0, t; }" : "=r"(a) : "l"(p));
    return a;
}
__device__ __forceinline__ void cp_async16(unsigned sdst, const void* gsrc) {
    asm volatile("cp.async.cg.shared.global [%0], [%1], 16;" :: "r"(sdst), "l"(gsrc));
}
__device__ __forceinline__ void ldm_x4(unsigned r[4], unsigned addr) {
    asm volatile("ldmatrix.sync.aligned.m8n8.x4.shared.b16 {%0,%1,%2,%3}, [%4];"
                 : "=r"(r[0]), "=r"(r[1]), "=r"(r[2]), "=r"(r[3]) : "r"(addr));
}
__device__ __forceinline__ void ldm_x2(unsigned r[2], unsigned addr) {
    asm volatile("ldmatrix.sync.aligned.m8n8.x2.shared.b16 {%0,%1}, [%2];"
                 : "=r"(r[0]), "=r"(r[1]) : "r"(addr));
}
__device__ __forceinline__ void mma_16816(float d[4], const unsigned a[4], unsigned b0, unsigned b1) {
    asm volatile("mma.sync.aligned.m16n8k16.row.col.f32.f16.f16.f32 "
        "{%0,%1,%2,%3}, {%4,%5,%6,%7}, {%8,%9}, {%0,%1,%2,%3};"
        : "+f"(d[0]), "+f"(d[1]), "+f"(d[2]), "+f"(d[3])
        : "r"(a[0]), "r"(a[1]), "r"(a[2]), "r"(a[3]), "r"(b0), "r"(b1));
}
__device__ __forceinline__ float lrelu(float v) { return (v > 0.f) ? v : 0.01f * v; }

// ---------------- prep: fp16 weights into swizzled K-major layouts ----------------
__global__ void prep_kernel(const float* __restrict__ W0,
                            const float* __restrict__ W1,
                            const float* __restrict__ W2) {
    int i = blockIdx.x * 256 + threadIdx.x;
    if (i < 32768) {                        // W0 [128 o][256 k], stride 512
        int o = i >> 8, k = i & 255;
        *(__half*)(g_W0s + tile_off(o, k, 512)) = __float2half(W0[o * 256 + k]);
    } else if (i < 32768 + 24576) {         // W1 [64 o][384 k], stride 768
        int j = i - 32768, o = j / 384, k = j - o * 384;
        *(__half*)(g_W1s + tile_off(o, k, 768)) = __float2half(W1[o * 384 + k]);
    } else if (i < 32768 + 24576 + 2560) {  // W2 [8 o][320 k], stride 640, rows>=5 zero
        int j = i - 32768 - 24576, o = j / 320, k = j - o * 320;
        float v = (o < 5) ? W2[o * 320 + k] : 0.f;
        *(__half*)(g_W2s + tile_off(o, k, 640)) = __float2half(v);
    }
}

// ---------------- transpose: (B,C,H,W) f32 -> (B,HW,C) f16 (unchanged, passing) ----------------
__global__ __launch_bounds__(256)
void transpose_kernel(const float* __restrict__ sf) {
    __shared__ float tile[32][33];
    const int b  = blockIdx.z;
    const int c0 = blockIdx.y * 32;
    const int p0 = blockIdx.x * 32;
    const int tx = threadIdx.x, ty = threadIdx.y;
    const int t  = ty * 32 + tx;
    const float* src = sf + (size_t)b * CC * HW;
    #pragma unroll
    for (int j = 0; j < 4; j++)
        tile[ty * 4 + j][tx] = src[(size_t)(c0 + ty * 4 + j) * HW + p0 + tx];
    __syncthreads();
    const int pr  = t >> 3;
    const int ch4 = t & 7;
    __half2 v0 = __floats2half2_rn(tile[4 * ch4 + 0][pr], tile[4 * ch4 + 1][pr]);
    __half2 v1 = __floats2half2_rn(tile[4 * ch4 + 2][pr], tile[4 * ch4 + 3][pr]);
    uint2 pkt = make_uint2(*(unsigned*)&v0, *(unsigned*)&v1);
    uint2* dst = (uint2*)(g_sfT + (size_t)b * HW * CC + (size_t)(p0 + pr) * CC + c0);
    dst[ch4] = pkt;
}

// ---------------- fused: gather + 3-layer MLP via mma.sync ----------------
__global__ __launch_bounds__(THREADS)
void maf_fused(const float* __restrict__ p, const float* __restrict__ cam,
               const float* __restrict__ b0, const float* __restrict__ b1,
               const float* __restrict__ b2, float* __restrict__ out)
{
    extern __shared__ char smem[];
    const unsigned sbase = smem_u32(smem);
    const int tid  = threadIdx.x;
    const int warp = tid >> 5;
    const int lane = tid & 31;
    const int tile = blockIdx.x;

    // stage W0 + W2 early (overlaps params + gather)
    {
        #pragma unroll
        for (int i = 0; i < 16; i++)
            cp_async16(sbase + SM_BUF + (tid + i * 256) * 16, g_W0s + (tid + i * 256) * 16);
        if (tid < 64) {
            #pragma unroll
            for (int i = 0; i < 5; i++)
                cp_async16(sbase + SM_W2 + (tid + i * 64) * 16, g_W2s + (tid + i * 64) * 16);
        }
        asm volatile("cp.async.commit_group;");
    }

    // point params -> smem
    float* pW   = (float*)(smem + SM_PRM);        // [4][128]
    int*   pOff = (int*)(smem + SM_PRM + 2048);   // [4][128]
    if (tid < TILE_P) {
        int gp = tile * TILE_P + tid;
        if (gp >= NPTS) gp = NPTS - 1;            // clamp (last tile only)
        const int b = gp / NN;
        float s  = cam[b * 3 + 0];
        float tx = cam[b * 3 + 1];
        float ty = cam[b * 3 + 2];
        float gx = (s * (p[gp * 3 + 0] + tx) + 1.f) * (0.5f * (WW - 1));
        float gy = (s * (p[gp * 3 + 1] + ty) + 1.f) * (0.5f * (HH - 1));
        float x0f = floorf(gx), y0f = floorf(gy);
        float wx1 = gx - x0f, wy1 = gy - y0f;
        float wx0 = 1.f - wx1, wy0 = 1.f - wy1;
        if (!(x0f       >= 0.f && x0f       <= (float)(WW - 1))) wx0 = 0.f;
        if (!(x0f + 1.f >= 0.f && x0f + 1.f <= (float)(WW - 1))) wx1 = 0.f;
        if (!(y0f       >= 0.f && y0f       <= (float)(HH - 1))) wy0 = 0.f;
        if (!(y0f + 1.f >= 0.f && y0f + 1.f <= (float)(HH - 1))) wy1 = 0.f;
        int ix0 = (int)fminf(fmaxf(x0f,       0.f), (float)(WW - 1));
        int ix1 = (int)fminf(fmaxf(x0f + 1.f, 0.f), (float)(WW - 1));
        int iy0 = (int)fminf(fmaxf(y0f,       0.f), (float)(HH - 1));
        int iy1 = (int)fminf(fmaxf(y0f + 1.f, 0.f), (float)(HH - 1));
        int base = b * HW;
        pOff[0 * 128 + tid] = (base + iy0 * WW + ix0) * CC;
        pOff[1 * 128 + tid] = (base + iy0 * WW + ix1) * CC;
        pOff[2 * 128 + tid] = (base + iy1 * WW + ix0) * CC;
        pOff[3 * 128 + tid] = (base + iy1 * WW + ix1) * CC;
        pW[0 * 128 + tid] = wx0 * wy0; pW[1 * 128 + tid] = wx1 * wy0;
        pW[2 * 128 + tid] = wx0 * wy1; pW[3 * 128 + tid] = wx1 * wy1;
    }
    __syncthreads();

    // gather: thread = (pt, ch-parity); fp16 blend -> swizzled feat tile
    {
        const int pt = tid >> 1;
        const float w00 = pW[0 * 128 + pt], w10 = pW[1 * 128 + pt];
        const float w01 = pW[2 * 128 + pt], w11 = pW[3 * 128 + pt];
        const int o00 = pOff[0 * 128 + pt], o10 = pOff[1 * 128 + pt];
        const int o01 = pOff[2 * 128 + pt], o11 = pOff[3 * 128 + pt];
        #pragma unroll 4
        for (int j = 0; j < 16; j++) {
            const int c = (tid & 1) * 8 + j * 16;   // 8-channel group
            uint4 A  = *(const uint4*)(g_sfT + o00 + c);
            uint4 Bv = *(const uint4*)(g_sfT + o10 + c);
            uint4 Cv = *(const uint4*)(g_sfT + o01 + c);
            uint4 Dv = *(const uint4*)(g_sfT + o11 + c);
            __half2 hh[4];
            #pragma unroll
            for (int q = 0; q < 4; q++) {
                float2 fa = __half22float2(((const __half2*)&A)[q]);
                float2 fb = __half22float2(((const __half2*)&Bv)[q]);
                float2 fc = __half22float2(((const __half2*)&Cv)[q]);
                float2 fd = __half22float2(((const __half2*)&Dv)[q]);
                float rx = w00 * fa.x + w10 * fb.x + w01 * fc.x + w11 * fd.x;
                float ry = w00 * fa.y + w10 * fb.y + w01 * fc.y + w11 * fd.y;
                hh[q] = __floats2half2_rn(rx, ry);
            }
            *(uint4*)(smem + SM_FEAT + tile_off(pt, c, 512)) = *(uint4*)hh;
        }
    }
    asm volatile("cp.async.wait_group 0;");
    __syncthreads();

    const int qr = lane >> 2;          // 0..7
    const int qc = (lane & 3) * 2;     // 0,2,4,6

    // ---------------- layer0: D0[128,128] = feat[128,256] x W0^T ----------------
    // warp: rows m0..m0+31 (warp&3), cols n0..n0+63 (warp>>2)
    float d0[2][8][4];
    #pragma unroll
    for (int i = 0; i < 2; i++)
        #pragma unroll
        for (int j = 0; j < 8; j++)
            #pragma unroll
            for (int q = 0; q < 4; q++) d0[i][j][q] = 0.f;
    {
        const int m0 = (warp & 3) * 32;
        const int n0 = (warp >> 2) * 64;
        const int ar = lane & 15, ak = (lane >> 4) * 8;                    // A frag lanes
        const int br = (lane & 7) + ((lane >> 4) << 3), bk = ((lane >> 3) & 1) * 8;  // B frag lanes
        #pragma unroll 4
        for (int k16 = 0; k16 < 16; k16++) {
            const int kk = k16 * 16;
            unsigned a[2][4];
            #pragma unroll
            for (int mt = 0; mt < 2; mt++)
                ldm_x4(a[mt], sbase + SM_FEAT + tile_off(m0 + mt * 16 + ar, kk + ak, 512));
            #pragma unroll
            for (int nb = 0; nb < 4; nb++) {
                unsigned bfr[4];
                ldm_x4(bfr, sbase + SM_BUF + tile_off(n0 + nb * 16 + br, kk + bk, 512));
                mma_16816(d0[0][nb * 2 + 0], a[0], bfr[0], bfr[1]);
                mma_16816(d0[0][nb * 2 + 1], a[0], bfr[2], bfr[3]);
                mma_16816(d0[1][nb * 2 + 0], a[1], bfr[0], bfr[1]);
                mma_16816(d0[1][nb * 2 + 1], a[1], bfr[2], bfr[3]);
            }
        }
    }
    __syncthreads();   // all warps done reading W0 from SM_BUF

    // stage W1 into SM_BUF (overlaps epilogue0)
    {
        #pragma unroll
        for (int i = 0; i < 12; i++)
            cp_async16(sbase + SM_BUF + (tid + i * 256) * 16, g_W1s + (tid + i * 256) * 16);
        asm volatile("cp.async.commit_group;");
    }

    // epilogue0: bias + leaky -> y0 fp16 (swizzled, stride 256)
    {
        const int m0 = (warp & 3) * 32;
        const int n0 = (warp >> 2) * 64;
        #pragma unroll
        for (int mt = 0; mt < 2; mt++)
            #pragma unroll
            for (int nt = 0; nt < 8; nt++) {
                int row = m0 + mt * 16 + qr;
                int o   = n0 + nt * 8 + qc;
                float bx = __ldg(b0 + o), by = __ldg(b0 + o + 1);
                __half2 h0 = __floats2half2_rn(lrelu(d0[mt][nt][0] + bx), lrelu(d0[mt][nt][1] + by));
                __half2 h1 = __floats2half2_rn(lrelu(d0[mt][nt][2] + bx), lrelu(d0[mt][nt][3] + by));
                *(__half2*)(smem + SM_Y0 + tile_off(row,     o, 256)) = h0;
                *(__half2*)(smem + SM_Y0 + tile_off(row + 8, o, 256)) = h1;
            }
    }
    asm volatile("cp.async.wait_group 0;");
    __syncthreads();

    // ---------------- layer1: D1[128,64] = [y0|feat] x W1^T ----------------
    float d1[2][4][4];
    #pragma unroll
    for (int i = 0; i < 2; i++)
        #pragma unroll
        for (int j = 0; j < 4; j++)
            #pragma unroll
            for (int q = 0; q < 4; q++) d1[i][j][q] = 0.f;
    {
        const int m0 = (warp & 3) * 32;
        const int n0 = (warp >> 2) * 32;
        const int ar = lane & 15, ak = (lane >> 4) * 8;
        const int br = (lane & 7) + ((lane >> 4) << 3), bk = ((lane >> 3) & 1) * 8;
        #pragma unroll 4
        for (int k16 = 0; k16 < 24; k16++) {
            const int kk = k16 * 16;
            const unsigned abase = (kk < 128) ? (sbase + SM_Y0) : (sbase + SM_FEAT);
            const int S    = (kk < 128) ? 256 : 512;
            const int kloc = (kk < 128) ? kk : (kk - 128);
            unsigned a[2][4];
            #pragma unroll
            for (int mt = 0; mt < 2; mt++)
                ldm_x4(a[mt], abase + tile_off(m0 + mt * 16 + ar, kloc + ak, S));
            #pragma unroll
            for (int nb = 0; nb < 2; nb++) {
                unsigned bfr[4];
                ldm_x4(bfr, sbase + SM_BUF + tile_off(n0 + nb * 16 + br, kk + bk, 768));
                mma_16816(d1[0][nb * 2 + 0], a[0], bfr[0], bfr[1]);
                mma_16816(d1[0][nb * 2 + 1], a[0], bfr[2], bfr[3]);
                mma_16816(d1[1][nb * 2 + 0], a[1], bfr[0], bfr[1]);
                mma_16816(d1[1][nb * 2 + 1], a[1], bfr[2], bfr[3]);
            }
        }
    }

    // epilogue1 -> y1 fp16 (stride 128); y1 region doesn't overlap W1
    {
        const int m0 = (warp & 3) * 32;
        const int n0 = (warp >> 2) * 32;
        #pragma unroll
        for (int mt = 0; mt < 2; mt++)
            #pragma unroll
            for (int nt = 0; nt < 4; nt++) {
                int row = m0 + mt * 16 + qr;
                int o   = n0 + nt * 8 + qc;
                float bx = __ldg(b1 + o), by = __ldg(b1 + o + 1);
                __half2 h0 = __floats2half2_rn(lrelu(d1[mt][nt][0] + bx), lrelu(d1[mt][nt][1] + by));
                __half2 h1 = __floats2half2_rn(lrelu(d1[mt][nt][2] + bx), lrelu(d1[mt][nt][3] + by));
                *(__half2*)(smem + SM_Y1 + tile_off(row,     o, 128)) = h0;
                *(__half2*)(smem + SM_Y1 + tile_off(row + 8, o, 128)) = h1;
            }
    }
    __syncthreads();

    // ---------------- layer2: D2[128,8] = [y1|feat] x W2^T ----------------
    float d2[4] = {0.f, 0.f, 0.f, 0.f};
    {
        const int m0 = warp * 16;
        const int ar = lane & 15, ak = (lane >> 4) * 8;
        const int br = lane & 7, bk = ((lane >> 3) & 1) * 8;
        #pragma unroll 4
        for (int k16 = 0; k16 < 20; k16++) {
            const int kk = k16 * 16;
            const unsigned abase = (kk < 64) ? (sbase + SM_Y1) : (sbase + SM_FEAT);
            const int S    = (kk < 64) ? 128 : 512;
            const int kloc = (kk < 64) ? kk : (kk - 64);
            unsigned a[4];
            ldm_x4(a, abase + tile_off(m0 + ar, kloc + ak, S));
            unsigned bfr[2];
            ldm_x2(bfr, sbase + SM_W2 + tile_off(br, kk + bk, 640));
            mma_16816(d2, a, bfr[0], bfr[1]);
        }
    }

    // epilogue2: relu + write out (5 valid cols)
    {
        const int m0 = warp * 16;
        #pragma unroll
        for (int half = 0; half < 2; half++) {
            int pt = m0 + half * 8 + qr;
            int gp = tile * TILE_P + pt;
            if (gp < NPTS) {
                int b = gp / NN;
                int n = gp - b * NN;
                float v0 = d2[half * 2 + 0] + __ldg(b2 + qc);
                if (qc < 5)     out[b * (5 * NN) + qc * NN + n]       = fmaxf(v0, 0.f);
                if (qc + 1 < 5) {
                    float v1 = d2[half * 2 + 1] + __ldg(b2 + qc + 1);
                    out[b * (5 * NN) + (qc + 1) * NN + n] = fmaxf(v1, 0.f);
                }
            }
        }
    }
}

extern "C" void kernel_launch(void* const* d_in, const int* in_sizes, int n_in,
                              void* d_out, int out_size) {
    const float* p   = (const float*)d_in[0];
    const float* cam = (const float*)d_in[1];
    const float* sf  = (const float*)d_in[2];
    const float* W0  = (const float*)d_in[3];
    const float* b0  = (const float*)d_in[4];
    const float* W1  = (const float*)d_in[5];
    const float* b1  = (const float*)d_in[6];
    const float* W2  = (const float*)d_in[7];
    const float* b2  = (const float*)d_in[8];
    float* out = (float*)d_out;

    prep_kernel<<<(32768 + 24576 + 2560 + 255) / 256, 256>>>(W0, W1, W2);

    dim3 tgrid(HW / 32, CC / 32, BB);
    transpose_kernel<<<tgrid, dim3(32, 8)>>>(sf);

    cudaFuncSetAttribute(maf_fused, cudaFuncAttributeMaxDynamicSharedMemorySize, SM_TOTAL);
    maf_fused<<<NTILES, THREADS, SM_TOTAL>>>(p, cam, b0, b1, b2, out);
}